// round 2
// baseline (speedup 1.0000x reference)
#include <cuda_runtime.h>
#include <cstdint>

#define NN 8192
#define HH 256
#define TOPK 16
#define NSEC 11
#define NEG_SLOPE 0.2f

// ---------------- device scratch (no allocations allowed) ----------------
__device__ __align__(16) float g_v1[HH];
__device__ __align__(16) float g_v2[HH];
__device__ __align__(16) float g_s1[NN];
__device__ __align__(16) float g_s2[NN];
__device__ int g_mask_mode;   // 0 = uint8, 1 = int32, 2 = float32

// ---------------- helpers ----------------
__device__ __forceinline__ bool is_active(const void* am, int i, int mode) {
    if (mode == 0) return ((const unsigned char*)am)[i] != 0;
    if (mode == 1) return ((const int*)am)[i] != 0;
    return ((const float*)am)[i] != 0.0f;
}

__device__ __forceinline__ unsigned long long umax64(unsigned long long a,
                                                     unsigned long long b) {
    return a > b ? a : b;
}

// ============================================================================
// Kernel 1 (2 blocks): block 0 detects mask dtype, block 1 computes
// v1 = W^T a[:H], v2 = W^T a[H:].
// ============================================================================
__global__ void k_init(const unsigned char* __restrict__ am,
                       const float* __restrict__ W,
                       const float* __restrict__ a) {
    if (blockIdx.x == 0) {
        // ---- detect active_mask storage layout (scan first NN bytes; safe in
        // every candidate layout). Deterministic. ----
        __shared__ int s_gt1, s_nz_off, s_nz_al;
        if (threadIdx.x == 0) { s_gt1 = 0; s_nz_off = 0; s_nz_al = 0; }
        __syncthreads();
        int l_gt1 = 0, l_off = 0, l_al = 0;
        for (int p = threadIdx.x; p < NN; p += blockDim.x) {
            unsigned char b = am[p];
            if (b > 1) l_gt1 = 1;
            if (b != 0) { if (p & 3) l_off = 1; else l_al = 1; }
        }
        if (l_gt1) atomicOr(&s_gt1, 1);
        if (l_off) atomicOr(&s_nz_off, 1);
        if (l_al)  atomicOr(&s_nz_al, 1);
        __syncthreads();
        if (threadIdx.x == 0) {
            int mode;
            if (s_gt1) mode = s_nz_al ? 0 : 2;  // f32 bytes only at p%4==2,3
            else       mode = s_nz_off ? 1 : 1, mode = s_nz_off ? 0 : 1;
            g_mask_mode = mode;
        }
    } else {
        // ---- proj: 256 threads; k split 4x64, each thread owns 4 columns ----
        __shared__ float sa[2 * HH];
        __shared__ float red[4][64][8];
        int t = threadIdx.x;
        sa[t]       = a[t];
        sa[t + 256] = a[t + 256];
        __syncthreads();
        int part = t >> 6;          // which k-chunk (0..3)
        int cg   = t & 63;          // float4 column group (0..63)
        int ks   = part * 64;
        float acc0 = 0.f, acc1 = 0.f, acc2 = 0.f, acc3 = 0.f;
        float acc4 = 0.f, acc5 = 0.f, acc6 = 0.f, acc7 = 0.f;
        const float4* W4 = (const float4*)W;
#pragma unroll 4
        for (int k = ks; k < ks + 64; k++) {
            float4 w = W4[k * 64 + cg];
            float a1 = sa[k], a2 = sa[256 + k];
            acc0 = fmaf(w.x, a1, acc0); acc1 = fmaf(w.y, a1, acc1);
            acc2 = fmaf(w.z, a1, acc2); acc3 = fmaf(w.w, a1, acc3);
            acc4 = fmaf(w.x, a2, acc4); acc5 = fmaf(w.y, a2, acc5);
            acc6 = fmaf(w.z, a2, acc6); acc7 = fmaf(w.w, a2, acc7);
        }
        red[part][cg][0] = acc0; red[part][cg][1] = acc1;
        red[part][cg][2] = acc2; red[part][cg][3] = acc3;
        red[part][cg][4] = acc4; red[part][cg][5] = acc5;
        red[part][cg][6] = acc6; red[part][cg][7] = acc7;
        __syncthreads();
        if (t < 64) {
#pragma unroll
            for (int j = 0; j < 8; j++) {
                float s = red[0][t][j] + red[1][t][j] + red[2][t][j] + red[3][t][j];
                if (j < 4) g_v1[4 * t + j]     = s;
                else       g_v2[4 * t + j - 4] = s;
            }
        }
    }
}

// ============================================================================
// Kernel 2: s1 = E @ v1, s2 = E @ v2.  One warp per row, float4 loads.
// ============================================================================
__global__ void k_scores(const float* __restrict__ E) {
    __shared__ float4 sv1[64], sv2[64];
    int t = threadIdx.x;               // 256 threads = 8 warps
    if (t < 64) {
        sv1[t] = ((const float4*)g_v1)[t];
        sv2[t] = ((const float4*)g_v2)[t];
    }
    __syncthreads();
    int wp = t >> 5, lane = t & 31;
    int row = blockIdx.x * 8 + wp;
    const float4* e4 = (const float4*)(E + (size_t)row * HH);
    float a1 = 0.f, a2 = 0.f;
#pragma unroll
    for (int c = 0; c < 2; c++) {
        int k = lane + c * 32;
        float4 x = e4[k];
        float4 v = sv1[k];
        float4 u = sv2[k];
        a1 = fmaf(x.x, v.x, fmaf(x.y, v.y, fmaf(x.z, v.z, fmaf(x.w, v.w, a1))));
        a2 = fmaf(x.x, u.x, fmaf(x.y, u.y, fmaf(x.z, u.z, fmaf(x.w, u.w, a2))));
    }
#pragma unroll
    for (int o = 16; o; o >>= 1) {
        a1 += __shfl_xor_sync(0xFFFFFFFFu, a1, o);
        a2 += __shfl_xor_sync(0xFFFFFFFFu, a2, o);
    }
    if (lane == 0) { g_s1[row] = a1; g_s2[row] = a2; }
}

// ============================================================================
// Kernel 3: per-sector top-16 (warp tournament, 2 barriers total) fused with
// output emission. One 1024-thread block per sector.
// Key = (monotone_u32(s2) << 32) | ~j  -> max-order == (s2 desc, idx asc),
// matching jax.lax.top_k tie-breaking. Key 0 is an impossible sentinel
// (low 32 bits ~j are nonzero for j < 2^32-1).
// ============================================================================
__global__ void __launch_bounds__(1024, 1)
k_topk_out(const int* __restrict__ sector, const void* __restrict__ am,
           float* __restrict__ out, int out_size) {
    int sec  = blockIdx.x;
    int tid  = threadIdx.x;            // 1024
    int lane = tid & 31, wp = tid >> 5;
    int mode = g_mask_mode;

    // ---- gather candidates: thread owns i = tid + t*1024, t in [0,8) ----
    unsigned long long cand[8];
#pragma unroll
    for (int t = 0; t < 8; t++) {
        int i = tid + (t << 10);
        unsigned long long key = 0ull;
        if (sector[i] == sec && is_active(am, i, mode)) {
            unsigned u = __float_as_uint(g_s2[i]);
            u = (u & 0x80000000u) ? ~u : (u | 0x80000000u);
            key = ((unsigned long long)u << 32) | (unsigned)(~i);
        }
        cand[t] = key;
    }

    // ---- level 1: each warp pops its top-16 via shfl-max rounds (no BAR) ----
    __shared__ unsigned long long warp_top[32][16];
#pragma unroll 1
    for (int r = 0; r < 16; r++) {
        unsigned long long m = cand[0];
#pragma unroll
        for (int j = 1; j < 8; j++) m = umax64(m, cand[j]);
        unsigned long long w = m;
#pragma unroll
        for (int o = 16; o; o >>= 1)
            w = umax64(w, __shfl_xor_sync(0xFFFFFFFFu, w, o));
        if (w != 0ull && m == w) {     // unique winner clears its element
            bool done = false;
#pragma unroll
            for (int j = 0; j < 8; j++)
                if (!done && cand[j] == w) { cand[j] = 0ull; done = true; }
        }
        if (lane == 0) warp_top[wp][r] = w;   // sorted desc per warp
    }
    __syncthreads();

    // ---- level 2: warp 0 merges 32 sorted 16-lists ----
    __shared__ int   s_idx[TOPK];
    __shared__ float s_w2[TOPK];
    __shared__ int   s_cnt;
    if (wp == 0) {
        int h = 0;
        int cnt = 0;
#pragma unroll 1
        for (int r = 0; r < 16; r++) {
            unsigned long long v = (h < 16) ? warp_top[lane][h] : 0ull;
            unsigned long long w = v;
#pragma unroll
            for (int o = 16; o; o >>= 1)
                w = umax64(w, __shfl_xor_sync(0xFFFFFFFFu, w, o));
            if (w != 0ull && v == w) h++;
            if (lane == 0 && w != 0ull) {
                int idx = (int)(~(unsigned)(w & 0xFFFFFFFFull));
                s_idx[r] = idx;
                s_w2[r]  = g_s2[idx];
                cnt = r + 1;
            }
        }
        if (lane == 0) {
            // fill remaining slots with smallest NON-member indices (the -inf
            // ties; jax top_k picks them in ascending index order)
            int k = cnt, j = 0;
            while (k < TOPK && j < NN) {
                bool mem = (sector[j] == sec) && is_active(am, j, mode);
                if (!mem) { s_idx[k] = j; s_w2[k] = 0.f; k++; }
                j++;
            }
            while (k < TOPK) { s_idx[k] = 0; s_w2[k] = 0.f; k++; }
            s_cnt = cnt;
        }
    }
    __syncthreads();

    // ---- output: each thread emits the 16-tuples for its sector rows ----
    int cnt = s_cnt;
    const int NT = NN * TOPK;
    bool w_idx = (out_size >= 2 * NT);
    bool w_val = (out_size >= 3 * NT);
#pragma unroll 1
    for (int t = 0; t < 8; t++) {
        int i = tid + (t << 10);
        if (sector[i] != sec) continue;
        bool act = is_active(am, i, mode);
        float s1 = act ? g_s1[i] : 0.f;
#pragma unroll
        for (int k = 0; k < TOPK; k += 4) {
            float wv[4], iv[4], vv[4];
#pragma unroll
            for (int q = 0; q < 4; q++) {
                int kk = k + q;
                if (!act) {
                    // whole row is -inf: top_k returns indices 0..15, invalid
                    wv[q] = 0.f; iv[q] = (float)kk; vv[q] = 0.f;
                } else if (kk < cnt) {
                    float x = s1 + s_w2[kk];
                    wv[q] = (x >= 0.f) ? x : NEG_SLOPE * x;  // leaky_relu, T=1
                    iv[q] = (float)s_idx[kk]; vv[q] = 1.f;
                } else {
                    wv[q] = 0.f; iv[q] = (float)s_idx[kk]; vv[q] = 0.f;
                }
            }
            int o = i * TOPK + k;
            *(float4*)&out[o] = make_float4(wv[0], wv[1], wv[2], wv[3]);
            if (w_idx) *(float4*)&out[NT + o]     = make_float4(iv[0], iv[1], iv[2], iv[3]);
            if (w_val) *(float4*)&out[2 * NT + o] = make_float4(vv[0], vv[1], vv[2], vv[3]);
        }
    }
}

extern "C" void kernel_launch(void* const* d_in, const int* in_sizes, int n_in,
                              void* d_out, int out_size) {
    const float* E      = (const float*)d_in[0];   // embeddings [N, H]
    const float* W      = (const float*)d_in[1];   // W [H, H]
    const float* a      = (const float*)d_in[2];   // a [2H]
    const int*   sector = (const int*)d_in[3];     // sector_ids [N]
    const void*  am     = d_in[4];                 // active_mask [N]
    float* out = (float*)d_out;

    k_init    <<<2, 256>>>((const unsigned char*)am, W, a);
    k_scores  <<<NN / 8, 256>>>(E);
    k_topk_out<<<NSEC, 1024>>>(sector, am, out, out_size);
}

// round 3
// speedup vs baseline: 1.4443x; 1.4443x over previous
#include <cuda_runtime.h>
#include <cstdint>

#define NN 8192
#define HH 256
#define TOPK 16
#define NSEC 11
#define NEG_SLOPE 0.2f
#define KCH 8            // split-K chunks for the W projection

// ---------------- device scratch (no allocations allowed) ----------------
__device__ __align__(16) float g_p1[KCH][HH];   // partial v1 per k-chunk
__device__ __align__(16) float g_p2[KCH][HH];   // partial v2 per k-chunk
__device__ __align__(16) float g_s1[NN];
__device__ __align__(16) float g_s2[NN];
__device__ int g_mask_mode;   // 0 = uint8, 1 = int32, 2 = float32

// ---------------- helpers ----------------
__device__ __forceinline__ bool is_active(const void* am, int i, int mode) {
    if (mode == 0) return ((const unsigned char*)am)[i] != 0;
    if (mode == 1) return ((const int*)am)[i] != 0;
    return ((const float*)am)[i] != 0.0f;
}

__device__ __forceinline__ unsigned long long umax64(unsigned long long a,
                                                     unsigned long long b) {
    return a > b ? a : b;
}

// ============================================================================
// Kernel A (9 blocks, 64 threads): blocks 0..7 compute split-K partials of
// v1 = W^T a[:H], v2 = W^T a[H:] (each block streams 32 rows of W = 32KB,
// fully coalesced float4). Block 8 detects the active_mask storage dtype.
// ============================================================================
__global__ void k_init(const unsigned char* __restrict__ am,
                       const float* __restrict__ W,
                       const float* __restrict__ a) {
    if (blockIdx.x < KCH) {
        int c  = blockIdx.x;
        int cg = threadIdx.x;           // float4 column group 0..63
        int k0 = c * (HH / KCH);        // 32 rows per chunk
        const float4* W4 = (const float4*)W;
        float4 acc1 = make_float4(0.f, 0.f, 0.f, 0.f);
        float4 acc2 = make_float4(0.f, 0.f, 0.f, 0.f);
#pragma unroll 8
        for (int k = k0; k < k0 + HH / KCH; k++) {
            float4 w = W4[k * 64 + cg];
            float a1 = __ldg(&a[k]), a2 = __ldg(&a[HH + k]);
            acc1.x = fmaf(w.x, a1, acc1.x); acc1.y = fmaf(w.y, a1, acc1.y);
            acc1.z = fmaf(w.z, a1, acc1.z); acc1.w = fmaf(w.w, a1, acc1.w);
            acc2.x = fmaf(w.x, a2, acc2.x); acc2.y = fmaf(w.y, a2, acc2.y);
            acc2.z = fmaf(w.z, a2, acc2.z); acc2.w = fmaf(w.w, a2, acc2.w);
        }
        ((float4*)g_p1[c])[cg] = acc1;
        ((float4*)g_p2[c])[cg] = acc2;
    } else {
        // ---- detect active_mask storage layout (scan first NN bytes; safe in
        // every candidate layout). Deterministic. ----
        __shared__ int s_gt1, s_nz_off, s_nz_al;
        if (threadIdx.x == 0) { s_gt1 = 0; s_nz_off = 0; s_nz_al = 0; }
        __syncthreads();
        int l_gt1 = 0, l_off = 0, l_al = 0;
        for (int p = threadIdx.x; p < NN; p += blockDim.x) {
            unsigned char b = am[p];
            if (b > 1) l_gt1 = 1;
            if (b != 0) { if (p & 3) l_off = 1; else l_al = 1; }
        }
        if (l_gt1) atomicOr(&s_gt1, 1);
        if (l_off) atomicOr(&s_nz_off, 1);
        if (l_al)  atomicOr(&s_nz_al, 1);
        __syncthreads();
        if (threadIdx.x == 0) {
            int mode;
            if (s_gt1) mode = s_nz_al ? 0 : 2;  // f32 truth bytes at p%4==2,3
            else       mode = s_nz_off ? 0 : 1;
            g_mask_mode = mode;
        }
    }
}

// ============================================================================
// Kernel B: reduce split-K partials to v1/v2 in smem (L2-resident reads),
// then s1 = E @ v1, s2 = E @ v2. One warp per row, float4 loads.
// ============================================================================
__global__ void k_scores(const float* __restrict__ E) {
    __shared__ float sv1[HH], sv2[HH];
    int t = threadIdx.x;               // 256 threads = 8 warps
    {
        float x1 = 0.f, x2 = 0.f;
#pragma unroll
        for (int c = 0; c < KCH; c++) {
            x1 += g_p1[c][t];
            x2 += g_p2[c][t];
        }
        sv1[t] = x1;
        sv2[t] = x2;
    }
    __syncthreads();
    int wp = t >> 5, lane = t & 31;
    int row = blockIdx.x * 8 + wp;
    const float4* e4 = (const float4*)(E + (size_t)row * HH);
    const float4* v4 = (const float4*)sv1;
    const float4* u4 = (const float4*)sv2;
    float a1 = 0.f, a2 = 0.f;
#pragma unroll
    for (int c = 0; c < 2; c++) {
        int k = lane + c * 32;
        float4 x = e4[k];
        float4 v = v4[k];
        float4 u = u4[k];
        a1 = fmaf(x.x, v.x, fmaf(x.y, v.y, fmaf(x.z, v.z, fmaf(x.w, v.w, a1))));
        a2 = fmaf(x.x, u.x, fmaf(x.y, u.y, fmaf(x.z, u.z, fmaf(x.w, u.w, a2))));
    }
#pragma unroll
    for (int o = 16; o; o >>= 1) {
        a1 += __shfl_xor_sync(0xFFFFFFFFu, a1, o);
        a2 += __shfl_xor_sync(0xFFFFFFFFu, a2, o);
    }
    if (lane == 0) { g_s1[row] = a1; g_s2[row] = a2; }
}

// ============================================================================
// Kernel C: per-sector top-16 (warp tournament, 2 barriers total) fused with
// output emission. One 1024-thread block per sector.
// Key = (monotone_u32(s2) << 32) | ~j  -> max-order == (s2 desc, idx asc),
// matching jax.lax.top_k tie-breaking. Key 0 is an impossible sentinel.
// ============================================================================
__global__ void __launch_bounds__(1024, 1)
k_topk_out(const int* __restrict__ sector, const void* __restrict__ am,
           float* __restrict__ out, int out_size) {
    int sec  = blockIdx.x;
    int tid  = threadIdx.x;            // 1024
    int lane = tid & 31, wp = tid >> 5;
    int mode = g_mask_mode;

    // ---- gather candidates: thread owns i = tid + t*1024, t in [0,8) ----
    unsigned long long cand[8];
#pragma unroll
    for (int t = 0; t < 8; t++) {
        int i = tid + (t << 10);
        unsigned long long key = 0ull;
        if (sector[i] == sec && is_active(am, i, mode)) {
            unsigned u = __float_as_uint(g_s2[i]);
            u = (u & 0x80000000u) ? ~u : (u | 0x80000000u);
            key = ((unsigned long long)u << 32) | (unsigned)(~i);
        }
        cand[t] = key;
    }

    // ---- level 1: each warp pops its top-16 via shfl-max rounds (no BAR) ----
    __shared__ unsigned long long warp_top[32][16];
#pragma unroll 1
    for (int r = 0; r < 16; r++) {
        unsigned long long m = cand[0];
#pragma unroll
        for (int j = 1; j < 8; j++) m = umax64(m, cand[j]);
        unsigned long long w = m;
#pragma unroll
        for (int o = 16; o; o >>= 1)
            w = umax64(w, __shfl_xor_sync(0xFFFFFFFFu, w, o));
        if (w != 0ull && m == w) {     // unique winner clears its element
            bool done = false;
#pragma unroll
            for (int j = 0; j < 8; j++)
                if (!done && cand[j] == w) { cand[j] = 0ull; done = true; }
        }
        if (lane == 0) warp_top[wp][r] = w;   // sorted desc per warp
    }
    __syncthreads();

    // ---- level 2: warp 0 merges 32 sorted 16-lists ----
    __shared__ int   s_idx[TOPK];
    __shared__ float s_w2[TOPK];
    __shared__ int   s_cnt;
    if (wp == 0) {
        int h = 0;
        int cnt = 0;
#pragma unroll 1
        for (int r = 0; r < 16; r++) {
            unsigned long long v = (h < 16) ? warp_top[lane][h] : 0ull;
            unsigned long long w = v;
#pragma unroll
            for (int o = 16; o; o >>= 1)
                w = umax64(w, __shfl_xor_sync(0xFFFFFFFFu, w, o));
            if (w != 0ull && v == w) h++;
            if (lane == 0 && w != 0ull) {
                int idx = (int)(~(unsigned)(w & 0xFFFFFFFFull));
                s_idx[r] = idx;
                s_w2[r]  = g_s2[idx];
                cnt = r + 1;
            }
        }
        if (lane == 0) {
            // fill remaining slots with smallest NON-member indices (the -inf
            // ties; jax top_k picks them in ascending index order)
            int k = cnt, j = 0;
            while (k < TOPK && j < NN) {
                bool mem = (sector[j] == sec) && is_active(am, j, mode);
                if (!mem) { s_idx[k] = j; s_w2[k] = 0.f; k++; }
                j++;
            }
            while (k < TOPK) { s_idx[k] = 0; s_w2[k] = 0.f; k++; }
            s_cnt = cnt;
        }
    }
    __syncthreads();

    // ---- output: each thread emits the 16-tuples for its sector rows ----
    int cnt = s_cnt;
    const int NT = NN * TOPK;
    bool w_idx = (out_size >= 2 * NT);
    bool w_val = (out_size >= 3 * NT);
#pragma unroll 1
    for (int t = 0; t < 8; t++) {
        int i = tid + (t << 10);
        if (sector[i] != sec) continue;
        bool act = is_active(am, i, mode);
        float s1 = act ? g_s1[i] : 0.f;
#pragma unroll
        for (int k = 0; k < TOPK; k += 4) {
            float wv[4], iv[4], vv[4];
#pragma unroll
            for (int q = 0; q < 4; q++) {
                int kk = k + q;
                if (!act) {
                    // whole row is -inf: top_k returns indices 0..15, invalid
                    wv[q] = 0.f; iv[q] = (float)kk; vv[q] = 0.f;
                } else if (kk < cnt) {
                    float x = s1 + s_w2[kk];
                    wv[q] = (x >= 0.f) ? x : NEG_SLOPE * x;  // leaky_relu, T=1
                    iv[q] = (float)s_idx[kk]; vv[q] = 1.f;
                } else {
                    wv[q] = 0.f; iv[q] = (float)s_idx[kk]; vv[q] = 0.f;
                }
            }
            int o = i * TOPK + k;
            *(float4*)&out[o] = make_float4(wv[0], wv[1], wv[2], wv[3]);
            if (w_idx) *(float4*)&out[NT + o]     = make_float4(iv[0], iv[1], iv[2], iv[3]);
            if (w_val) *(float4*)&out[2 * NT + o] = make_float4(vv[0], vv[1], vv[2], vv[3]);
        }
    }
}

extern "C" void kernel_launch(void* const* d_in, const int* in_sizes, int n_in,
                              void* d_out, int out_size) {
    const float* E      = (const float*)d_in[0];   // embeddings [N, H]
    const float* W      = (const float*)d_in[1];   // W [H, H]
    const float* a      = (const float*)d_in[2];   // a [2H]
    const int*   sector = (const int*)d_in[3];     // sector_ids [N]
    const void*  am     = d_in[4];                 // active_mask [N]
    float* out = (float*)d_out;

    k_init    <<<KCH + 1, 64>>>((const unsigned char*)am, W, a);
    k_scores  <<<NN / 8, 256>>>(E);
    k_topk_out<<<NSEC, 1024>>>(sector, am, out, out_size);
}

// round 4
// speedup vs baseline: 1.6545x; 1.1455x over previous
#include <cuda_runtime.h>
#include <cstdint>

#define NN 8192
#define HH 256
#define TOPK 16
#define NSEC 11
#define NEG_SLOPE 0.2f
#define KCH 8            // split-K chunks for the W projection

// ---------------- device scratch (no allocations allowed) ----------------
__device__ __align__(16) float g_p1[KCH][HH];   // partial v1 per k-chunk
__device__ __align__(16) float g_p2[KCH][HH];   // partial v2 per k-chunk
__device__ __align__(16) float g_s1[NN];
__device__ __align__(16) float g_s2[NN];
__device__ int g_mask_mode;   // 0 = uint8, 1 = int32, 2 = float32

// ---------------- helpers ----------------
__device__ __forceinline__ bool is_active(const void* am, int i, int mode) {
    if (mode == 0) return ((const unsigned char*)am)[i] != 0;
    if (mode == 1) return ((const int*)am)[i] != 0;
    return ((const float*)am)[i] != 0.0f;
}

__device__ __forceinline__ unsigned long long umax64(unsigned long long a,
                                                     unsigned long long b) {
    return a > b ? a : b;
}

// ============================================================================
// Kernel A (KCH+1 blocks, 256 threads): blocks 0..KCH-1 compute split-K
// partials of v1 = W^T a[:H], v2 = W^T a[H:] (each block streams 32 rows of
// W = 32KB with 2048 float4 loads in flight). Block KCH detects the
// active_mask storage dtype with uint4 loads.
// ============================================================================
__global__ void k_init(const unsigned char* __restrict__ am,
                       const float* __restrict__ W,
                       const float* __restrict__ a) {
    if (blockIdx.x < KCH) {
        int c   = blockIdx.x;
        int t   = threadIdx.x;          // 256
        int cg  = t & 63;               // float4 column group 0..63
        int sub = t >> 6;               // k sub-split 0..3
        int k0  = c * (HH / KCH) + sub * 8;   // 8 rows each
        const float4* W4 = (const float4*)W;
        float4 acc1 = make_float4(0.f, 0.f, 0.f, 0.f);
        float4 acc2 = make_float4(0.f, 0.f, 0.f, 0.f);
#pragma unroll
        for (int k = k0; k < k0 + 8; k++) {
            float4 w = W4[k * 64 + cg];
            float a1 = __ldg(&a[k]), a2 = __ldg(&a[HH + k]);
            acc1.x = fmaf(w.x, a1, acc1.x); acc1.y = fmaf(w.y, a1, acc1.y);
            acc1.z = fmaf(w.z, a1, acc1.z); acc1.w = fmaf(w.w, a1, acc1.w);
            acc2.x = fmaf(w.x, a2, acc2.x); acc2.y = fmaf(w.y, a2, acc2.y);
            acc2.z = fmaf(w.z, a2, acc2.z); acc2.w = fmaf(w.w, a2, acc2.w);
        }
        __shared__ float4 r1[4][64], r2[4][64];
        r1[sub][cg] = acc1;
        r2[sub][cg] = acc2;
        __syncthreads();
        if (t < 64) {
            float4 s1 = r1[0][t], s2 = r2[0][t];
#pragma unroll
            for (int s = 1; s < 4; s++) {
                float4 x = r1[s][t], y = r2[s][t];
                s1.x += x.x; s1.y += x.y; s1.z += x.z; s1.w += x.w;
                s2.x += y.x; s2.y += y.y; s2.z += y.z; s2.w += y.w;
            }
            ((float4*)g_p1[c])[t] = s1;
            ((float4*)g_p2[c])[t] = s2;
        }
    } else {
        // ---- detect active_mask storage layout: scan first NN bytes as
        // uint4 (safe in every candidate layout). Deterministic. ----
        int t = threadIdx.x;            // 256
        const uint4* am4 = (const uint4*)am;
        unsigned gt1 = 0, nz_off = 0, nz_al = 0;
#pragma unroll
        for (int it = 0; it < NN / (256 * 16); it++) {   // 2 iterations
            uint4 v = am4[t + it * 256];
            unsigned ws[4] = {v.x, v.y, v.z, v.w};
#pragma unroll
            for (int j = 0; j < 4; j++) {
                unsigned w = ws[j];
                gt1    |= (w & 0xFEFEFEFEu);  // any byte with bits 1..7 set
                nz_al  |= (w & 0x000000FFu);  // byte at p%4==0 (little-endian)
                nz_off |= (w & 0xFFFFFF00u);  // bytes at p%4!=0
            }
        }
        // warp-ballot reduce, then smem across warps
        __shared__ unsigned s_g[8], s_o[8], s_a[8];
        unsigned bg = __ballot_sync(0xFFFFFFFFu, gt1 != 0);
        unsigned bo = __ballot_sync(0xFFFFFFFFu, nz_off != 0);
        unsigned ba = __ballot_sync(0xFFFFFFFFu, nz_al != 0);
        if ((t & 31) == 0) { s_g[t >> 5] = bg; s_o[t >> 5] = bo; s_a[t >> 5] = ba; }
        __syncthreads();
        if (t == 0) {
            unsigned G = 0, O = 0, A = 0;
#pragma unroll
            for (int j = 0; j < 8; j++) { G |= s_g[j]; O |= s_o[j]; A |= s_a[j]; }
            int mode;
            if (G) mode = A ? 0 : 2;    // f32 truth bytes live at p%4==2,3
            else   mode = O ? 0 : 1;
            g_mask_mode = mode;
        }
    }
}

// ============================================================================
// Kernel B: reduce split-K partials to v1/v2 in smem (L2-resident reads),
// then s1 = E @ v1, s2 = E @ v2. One warp per row, 16 rows / 512 thr per blk.
// ============================================================================
__global__ void __launch_bounds__(512)
k_scores(const float* __restrict__ E) {
    __shared__ float sv1[HH], sv2[HH];
    int t = threadIdx.x;               // 512 = 16 warps
    if (t < HH) {
        float x1 = 0.f, x2 = 0.f;
#pragma unroll
        for (int c = 0; c < KCH; c++) {
            x1 += g_p1[c][t];
            x2 += g_p2[c][t];
        }
        sv1[t] = x1;
        sv2[t] = x2;
    }
    __syncthreads();
    int wp = t >> 5, lane = t & 31;
    int row = blockIdx.x * 16 + wp;
    const float4* e4 = (const float4*)(E + (size_t)row * HH);
    const float4* v4 = (const float4*)sv1;
    const float4* u4 = (const float4*)sv2;
    float a1 = 0.f, a2 = 0.f;
#pragma unroll
    for (int c = 0; c < 2; c++) {
        int k = lane + c * 32;
        float4 x = e4[k];
        float4 v = v4[k];
        float4 u = u4[k];
        a1 = fmaf(x.x, v.x, fmaf(x.y, v.y, fmaf(x.z, v.z, fmaf(x.w, v.w, a1))));
        a2 = fmaf(x.x, u.x, fmaf(x.y, u.y, fmaf(x.z, u.z, fmaf(x.w, u.w, a2))));
    }
#pragma unroll
    for (int o = 16; o; o >>= 1) {
        a1 += __shfl_xor_sync(0xFFFFFFFFu, a1, o);
        a2 += __shfl_xor_sync(0xFFFFFFFFu, a2, o);
    }
    if (lane == 0) { g_s1[row] = a1; g_s2[row] = a2; }
}

// ============================================================================
// Kernel C: per-sector top-16 (warp tournament, 2 barriers total) fused with
// output emission. One 1024-thread block per sector.
// Key = (monotone_u32(s2) << 32) | ~j  -> max-order == (s2 desc, idx asc),
// matching jax.lax.top_k tie-breaking. Key 0 is an impossible sentinel.
// ============================================================================
__global__ void __launch_bounds__(1024, 1)
k_topk_out(const int* __restrict__ sector, const void* __restrict__ am,
           float* __restrict__ out, int out_size) {
    int sec  = blockIdx.x;
    int tid  = threadIdx.x;            // 1024
    int lane = tid & 31, wp = tid >> 5;
    int mode = g_mask_mode;

    // ---- gather candidates: thread owns i = tid + t*1024, t in [0,8) ----
    unsigned long long cand[8];
#pragma unroll
    for (int t = 0; t < 8; t++) {
        int i = tid + (t << 10);
        unsigned long long key = 0ull;
        if (sector[i] == sec && is_active(am, i, mode)) {
            unsigned u = __float_as_uint(g_s2[i]);
            u = (u & 0x80000000u) ? ~u : (u | 0x80000000u);
            key = ((unsigned long long)u << 32) | (unsigned)(~i);
        }
        cand[t] = key;
    }

    // ---- level 1: each warp pops its top-16 via shfl-max rounds (no BAR) ----
    __shared__ unsigned long long warp_top[32][16];
#pragma unroll 1
    for (int r = 0; r < 16; r++) {
        unsigned long long m = cand[0];
#pragma unroll
        for (int j = 1; j < 8; j++) m = umax64(m, cand[j]);
        unsigned long long w = m;
#pragma unroll
        for (int o = 16; o; o >>= 1)
            w = umax64(w, __shfl_xor_sync(0xFFFFFFFFu, w, o));
        if (w != 0ull && m == w) {     // unique winner clears its element
            bool done = false;
#pragma unroll
            for (int j = 0; j < 8; j++)
                if (!done && cand[j] == w) { cand[j] = 0ull; done = true; }
        }
        if (lane == 0) warp_top[wp][r] = w;   // sorted desc per warp
    }
    __syncthreads();

    // ---- level 2: warp 0 merges 32 sorted 16-lists ----
    __shared__ int   s_idx[TOPK];
    __shared__ float s_w2[TOPK];
    __shared__ int   s_cnt;
    if (wp == 0) {
        int h = 0;
        int cnt = 0;
#pragma unroll 1
        for (int r = 0; r < 16; r++) {
            unsigned long long v = (h < 16) ? warp_top[lane][h] : 0ull;
            unsigned long long w = v;
#pragma unroll
            for (int o = 16; o; o >>= 1)
                w = umax64(w, __shfl_xor_sync(0xFFFFFFFFu, w, o));
            if (w != 0ull && v == w) h++;
            if (lane == 0 && w != 0ull) {
                int idx = (int)(~(unsigned)(w & 0xFFFFFFFFull));
                s_idx[r] = idx;
                s_w2[r]  = g_s2[idx];
                cnt = r + 1;
            }
        }
        if (lane == 0) {
            // fill remaining slots with smallest NON-member indices (the -inf
            // ties; jax top_k picks them in ascending index order)
            int k = cnt, j = 0;
            while (k < TOPK && j < NN) {
                bool mem = (sector[j] == sec) && is_active(am, j, mode);
                if (!mem) { s_idx[k] = j; s_w2[k] = 0.f; k++; }
                j++;
            }
            while (k < TOPK) { s_idx[k] = 0; s_w2[k] = 0.f; k++; }
            s_cnt = cnt;
        }
    }
    __syncthreads();

    // ---- output: each thread emits the 16-tuples for its sector rows ----
    int cnt = s_cnt;
    const int NT = NN * TOPK;
    bool w_idx = (out_size >= 2 * NT);
    bool w_val = (out_size >= 3 * NT);
#pragma unroll 1
    for (int t = 0; t < 8; t++) {
        int i = tid + (t << 10);
        if (sector[i] != sec) continue;
        bool act = is_active(am, i, mode);
        float s1 = act ? g_s1[i] : 0.f;
#pragma unroll
        for (int k = 0; k < TOPK; k += 4) {
            float wv[4], iv[4], vv[4];
#pragma unroll
            for (int q = 0; q < 4; q++) {
                int kk = k + q;
                if (!act) {
                    // whole row is -inf: top_k returns indices 0..15, invalid
                    wv[q] = 0.f; iv[q] = (float)kk; vv[q] = 0.f;
                } else if (kk < cnt) {
                    float x = s1 + s_w2[kk];
                    wv[q] = (x >= 0.f) ? x : NEG_SLOPE * x;  // leaky_relu, T=1
                    iv[q] = (float)s_idx[kk]; vv[q] = 1.f;
                } else {
                    wv[q] = 0.f; iv[q] = (float)s_idx[kk]; vv[q] = 0.f;
                }
            }
            int o = i * TOPK + k;
            *(float4*)&out[o] = make_float4(wv[0], wv[1], wv[2], wv[3]);
            if (w_idx) *(float4*)&out[NT + o]     = make_float4(iv[0], iv[1], iv[2], iv[3]);
            if (w_val) *(float4*)&out[2 * NT + o] = make_float4(vv[0], vv[1], vv[2], vv[3]);
        }
    }
}

extern "C" void kernel_launch(void* const* d_in, const int* in_sizes, int n_in,
                              void* d_out, int out_size) {
    const float* E      = (const float*)d_in[0];   // embeddings [N, H]
    const float* W      = (const float*)d_in[1];   // W [H, H]
    const float* a      = (const float*)d_in[2];   // a [2H]
    const int*   sector = (const int*)d_in[3];     // sector_ids [N]
    const void*  am     = d_in[4];                 // active_mask [N]
    float* out = (float*)d_out;

    k_init    <<<KCH + 1, 256>>>((const unsigned char*)am, W, a);
    k_scores  <<<NN / 16, 512>>>(E);
    k_topk_out<<<NSEC, 1024>>>(sector, am, out, out_size);
}